// round 6
// baseline (speedup 1.0000x reference)
#include <cuda_runtime.h>
#include <cuda_fp16.h>

#define N0V   8192
#define N1V   100000
#define N2V   300000
#define KNBR  32
#define DD    64

typedef unsigned long long u64t;

#define PACKU64(out, lo, hi)  asm("mov.b64 %0, {%1, %2};" : "=l"(out) : "f"(lo), "f"(hi))
#define SPLATF64(out, v)      asm("mov.b64 %0, {%1, %1};" : "=l"(out) : "f"(v))
#define UNPACKF64(lo, hi, in) asm("mov.b64 {%0, %1}, %2;" : "=f"(lo), "=f"(hi) : "l"(in))
#define FFMA2(acc, a, b)      asm("fma.rn.f32x2 %0, %1, %2, %0;" : "+l"(acc) : "l"(a), "l"(b))

#define CP_ASYNC16(dst, src) \
    asm volatile("cp.async.cg.shared.global [%0], [%1], 16;" :: "r"(dst), "l"(src))
#define CP_COMMIT()   asm volatile("cp.async.commit_group;" ::: "memory")
#define CP_WAIT(n)    asm volatile("cp.async.wait_group %0;" :: "n"(n) : "memory")

// Scratch (device globals — allocation in kernel_launch is forbidden).
__device__ __half g_v2h[(size_t)N2V * DD];   // 38.4 MB (L2-resident gather target)
__device__ __half g_h1h[(size_t)N1V * DD];   // 12.8 MB

// ---------------------------------------------------------------------------
// Kernel A: v2h = half(feats[node_ids2]); 2 rows per thread for MLP.
// ---------------------------------------------------------------------------
__global__ void gather_v2h_kernel(const float* __restrict__ feats,
                                  const int*   __restrict__ node_ids2)
{
    int t = blockIdx.x * blockDim.x + threadIdx.x;
    const int half_total = (N2V / 2) * (DD / 4);
    if (t >= half_total) return;
    int row  = t >> 4;
    int c    = t & 15;
    int row2 = row + N2V / 2;
    int s1 = __ldg(node_ids2 + row);
    int s2 = __ldg(node_ids2 + row2);
    float4 v1 = __ldg((const float4*)(feats + (size_t)s1 * DD) + c);
    float4 v2 = __ldg((const float4*)(feats + (size_t)s2 * DD) + c);

    __half2 a0 = __floats2half2_rn(v1.x, v1.y);
    __half2 a1 = __floats2half2_rn(v1.z, v1.w);
    __half2 b0 = __floats2half2_rn(v2.x, v2.y);
    __half2 b1 = __floats2half2_rn(v2.z, v2.w);
    uint2 p1, p2;
    p1.x = *(unsigned int*)&a0;  p1.y = *(unsigned int*)&a1;
    p2.x = *(unsigned int*)&b0;  p2.y = *(unsigned int*)&b1;
    ((uint2*)g_v2h)[(size_t)row  * 16 + c] = p1;
    ((uint2*)g_v2h)[(size_t)row2 * 16 + c] = p2;
}

// ---------------------------------------------------------------------------
// Kernel B/C: block of 256 threads -> 64 output rows.
// Phase 1: each warp handles 8 rows sequentially with a 2-stage cp.async
//          pipeline: row r+1's 32 neighbor rows (4KB) stream into smem
//          (fire-and-forget LDGSTS, L1 bypass) while row r is reduced from
//          smem with conflict-free LDS + HADD2. fp32 aggregate -> sAgg.
// Phase 2: block GEMM  relu(sAgg @ W + b)  with f32x2 FMAs (unchanged R5).
//
// Dynamic smem: sW (16KB) | sAgg 64x66 f32 (16.5KB) | sKV 8 warps x 2 stages
//               x 32 nbr x 128B (64KB)  => 98816 B.
// ---------------------------------------------------------------------------
template<bool HALF_OUT>
__global__ void __launch_bounds__(256) agg_gemm_pipe_kernel(
    const __half*  __restrict__ vsrc,   // [nsrc][DD] halfs, rows 128B aligned
    const int*     __restrict__ nbr,    // [nrows][KNBR]
    const float*   __restrict__ W,      // [DD][DD] row-major
    const float*   __restrict__ bias,   // [DD]
    void*          __restrict__ outp,   // [nrows][DD] half or float
    int nrows)
{
    extern __shared__ char dyn[];
    float* sW = (float*)dyn;                               // 16384 B
    float (*sAgg)[66] = (float (*)[66])(dyn + 16384);      // 16896 B
    __half* sKV = (__half*)(dyn + 16384 + 16896);          // 65536 B

    const int tid  = threadIdx.x;
    const int lane = tid & 31;
    const int warp = tid >> 5;

    // Per-warp staging buffers (2 stages x 2048 halfs).
    __half* kvbase = sKV + (size_t)warp * 4096;
    unsigned kv_s0 = (unsigned)__cvta_generic_to_shared(kvbase);
    unsigned kv_s1 = kv_s0 + 4096;   // bytes

    // Stage W (coalesced float4).
    #pragma unroll
    for (int i = tid; i < DD * DD / 4; i += 256)
        ((float4*)sW)[i] = __ldg((const float4*)W + i);

    // ---------------- Phase 1: pipelined gather-mean ----------------
    const int rowbase = blockIdx.x * 64 + warp * 8;
    const char* vbytes = (const char*)vsrc;

    // lane -> (neighbor sub-slot, 16B chunk)
    const int sub  = lane >> 3;        // 0..3  : neighbor = sub + 4*i
    const int choff = (lane & 7) * 16; // byte offset within 128B row

    // Issue all 8 cp.async chunks for one row into stage buffer `kvs`.
    auto issue_row = [&](int row, unsigned kvs) {
        int cr = min(row, nrows - 1);
        int myidx = __ldg(nbr + (size_t)cr * KNBR + lane);
        #pragma unroll
        for (int i = 0; i < 8; ++i) {
            int n = sub + 4 * i;
            int idx = __shfl_sync(0xffffffffu, myidx, n);
            const char* src = vbytes + (size_t)idx * 128 + choff;
            unsigned dst = kvs + n * 128 + choff;
            CP_ASYNC16(dst, src);
        }
        CP_COMMIT();
    };

    issue_row(rowbase, kv_s0);

    #pragma unroll 1
    for (int r = 0; r < 8; ++r) {
        unsigned cur = (r & 1) ? kv_s1 : kv_s0;
        unsigned nxt = (r & 1) ? kv_s0 : kv_s1;
        if (r < 7) {
            issue_row(rowbase + r + 1, nxt);
            CP_WAIT(1);          // current row's group complete
        } else {
            CP_WAIT(0);
        }
        __syncwarp();

        // Reduce 32 neighbor rows: lane owns dims (2l, 2l+1).
        const __half2* kvh = (const __half2*)(kvbase + ((r & 1) ? 2048 : 0));
        float sx = 0.f, sy = 0.f;
        #pragma unroll
        for (int n = 0; n < 32; n += 2) {
            __half2 h0 = kvh[n * 32 + lane];
            __half2 h1 = kvh[(n + 1) * 32 + lane];
            float2 f = __half22float2(__hadd2(h0, h1));
            sx += f.x;  sy += f.y;
        }
        const float inv = 1.0f / KNBR;
        *(float2*)&sAgg[warp * 8 + r][2 * lane] = make_float2(sx * inv, sy * inv);
        __syncwarp();
    }
    __syncthreads();

    // ---------------- Phase 2: GEMM + bias + ReLU ----------------
    const int rp   = tid >> 3;        // 0..31 -> rows 2rp, 2rp+1
    const int col0 = (tid & 7) * 8;   // 8 consecutive output cols

    float4 bv0 = __ldg((const float4*)(bias + col0));
    float4 bv1 = __ldg((const float4*)(bias + col0 + 4));
    u64t acc0[4], acc1[4];
    PACKU64(acc0[0], bv0.x, bv0.y);  PACKU64(acc0[1], bv0.z, bv0.w);
    PACKU64(acc0[2], bv1.x, bv1.y);  PACKU64(acc0[3], bv1.z, bv1.w);
    acc1[0] = acc0[0];  acc1[1] = acc0[1];  acc1[2] = acc0[2];  acc1[3] = acc0[3];

    #pragma unroll
    for (int k = 0; k < DD; ++k) {
        float a0 = sAgg[2 * rp][k];
        float a1 = sAgg[2 * rp + 1][k];
        u64t s0, s1;
        SPLATF64(s0, a0);
        SPLATF64(s1, a1);
        const ulonglong2 w01 = *(const ulonglong2*)&sW[k * DD + col0];
        const ulonglong2 w23 = *(const ulonglong2*)&sW[k * DD + col0 + 4];
        FFMA2(acc0[0], s0, w01.x);  FFMA2(acc0[1], s0, w01.y);
        FFMA2(acc0[2], s0, w23.x);  FFMA2(acc0[3], s0, w23.y);
        FFMA2(acc1[0], s1, w01.x);  FFMA2(acc1[1], s1, w01.y);
        FFMA2(acc1[2], s1, w23.x);  FFMA2(acc1[3], s1, w23.y);
    }

    #pragma unroll
    for (int r = 0; r < 2; ++r) {
        int grow = blockIdx.x * 64 + 2 * rp + r;
        if (grow >= nrows) continue;
        const u64t* acc = r ? acc1 : acc0;
        float o[8];
        #pragma unroll
        for (int j = 0; j < 4; ++j) {
            float lo, hi;
            UNPACKF64(lo, hi, acc[j]);
            o[2 * j]     = fmaxf(lo, 0.f);
            o[2 * j + 1] = fmaxf(hi, 0.f);
        }
        if (HALF_OUT) {
            __half2 h[4];
            #pragma unroll
            for (int j = 0; j < 4; ++j) h[j] = __floats2half2_rn(o[2 * j], o[2 * j + 1]);
            *(uint4*)((__half*)outp + (size_t)grow * DD + col0) = *(uint4*)h;
        } else {
            float* op = (float*)outp + (size_t)grow * DD + col0;
            *(float4*)op       = make_float4(o[0], o[1], o[2], o[3]);
            *(float4*)(op + 4) = make_float4(o[4], o[5], o[6], o[7]);
        }
    }
}

// ---------------------------------------------------------------------------
// Inputs: 0 feats, 1 W0, 2 b0, 3 W1, 4 b1, 5 neigh_idx0, 6 neigh_idx1,
//         7 node_ids1 (unused), 8 node_ids2
// ---------------------------------------------------------------------------
#define DYN_SMEM (16384 + 16896 + 65536)

extern "C" void kernel_launch(void* const* d_in, const int* in_sizes, int n_in,
                              void* d_out, int out_size)
{
    const float* feats      = (const float*)d_in[0];
    const float* W0         = (const float*)d_in[1];
    const float* b0         = (const float*)d_in[2];
    const float* W1         = (const float*)d_in[3];
    const float* b1         = (const float*)d_in[4];
    const int*   neigh_idx0 = (const int*)  d_in[5];
    const int*   neigh_idx1 = (const int*)  d_in[6];
    const int*   node_ids2  = (const int*)  d_in[8];
    float*       out        = (float*)d_out;

    __half* v2h; cudaGetSymbolAddress((void**)&v2h, g_v2h);
    __half* h1h; cudaGetSymbolAddress((void**)&h1h, g_h1h);

    cudaFuncSetAttribute(agg_gemm_pipe_kernel<true>,
                         cudaFuncAttributeMaxDynamicSharedMemorySize, DYN_SMEM);
    cudaFuncSetAttribute(agg_gemm_pipe_kernel<false>,
                         cudaFuncAttributeMaxDynamicSharedMemorySize, DYN_SMEM);

    {
        const int half_total = (N2V / 2) * (DD / 4);
        gather_v2h_kernel<<<(half_total + 255) / 256, 256>>>(feats, node_ids2);
    }
    agg_gemm_pipe_kernel<true ><<<(N1V + 63) / 64, 256, DYN_SMEM>>>(
        v2h, neigh_idx1, W0, b0, (void*)h1h, N1V);
    agg_gemm_pipe_kernel<false><<<(N0V + 63) / 64, 256, DYN_SMEM>>>(
        h1h, neigh_idx0, W1, b1, (void*)out, N0V);
}

// round 7
// speedup vs baseline: 1.2498x; 1.2498x over previous
#include <cuda_runtime.h>
#include <cuda_fp16.h>

#define N0V   8192
#define N1V   100000
#define N2V   300000
#define KNBR  32
#define DD    64

typedef unsigned long long u64t;

#define PACKU64(out, lo, hi)  asm("mov.b64 %0, {%1, %2};" : "=l"(out) : "f"(lo), "f"(hi))
#define SPLATF64(out, v)      asm("mov.b64 %0, {%1, %1};" : "=l"(out) : "f"(v))
#define UNPACKF64(lo, hi, in) asm("mov.b64 {%0, %1}, %2;" : "=f"(lo), "=f"(hi) : "l"(in))
#define FFMA2(acc, a, b)      asm("fma.rn.f32x2 %0, %1, %2, %0;" : "+l"(acc) : "l"(a), "l"(b))

// Scratch (device globals — allocation in kernel_launch is forbidden).
__device__ __half g_v2h[(size_t)N2V * DD];    // 38.4 MB gather target
__device__ __half g_agg1[(size_t)N1V * DD];   // 12.8 MB hop-1 aggregates
__device__ __half g_h1h[(size_t)N1V * DD];    // 12.8 MB hop-1 activations

// ---------------------------------------------------------------------------
// K1: v2h = half(feats[node_ids2]); 2 rows per thread for MLP.
// ---------------------------------------------------------------------------
__global__ void gather_v2h_kernel(const float* __restrict__ feats,
                                  const int*   __restrict__ node_ids2)
{
    int t = blockIdx.x * blockDim.x + threadIdx.x;
    const int half_total = (N2V / 2) * (DD / 4);
    if (t >= half_total) return;
    int row  = t >> 4;
    int c    = t & 15;
    int row2 = row + N2V / 2;
    int s1 = __ldg(node_ids2 + row);
    int s2 = __ldg(node_ids2 + row2);
    float4 v1 = __ldg((const float4*)(feats + (size_t)s1 * DD) + c);
    float4 v2 = __ldg((const float4*)(feats + (size_t)s2 * DD) + c);

    __half2 a0 = __floats2half2_rn(v1.x, v1.y);
    __half2 a1 = __floats2half2_rn(v1.z, v1.w);
    __half2 b0 = __floats2half2_rn(v2.x, v2.y);
    __half2 b1 = __floats2half2_rn(v2.z, v2.w);
    uint2 p1, p2;
    p1.x = *(unsigned int*)&a0;  p1.y = *(unsigned int*)&a1;
    p2.x = *(unsigned int*)&b0;  p2.y = *(unsigned int*)&b1;
    ((uint2*)g_v2h)[(size_t)row  * 16 + c] = p1;
    ((uint2*)g_v2h)[(size_t)row2 * 16 + c] = p2;
}

// ---------------------------------------------------------------------------
// K2: pure gather-mean, wide-load variant.
// Warp handles 2 rows. One LDG.128 fetches 4 whole neighbor rows
// (lane = (subgroup=lane>>3, 16B-chunk=lane&7)): 8 LDG.128 per row instead
// of 32 LDG.64 -> 1/4 LSU dispatch. fp16 accum depth<=5, fp32 butterfly.
// ---------------------------------------------------------------------------
__global__ void __launch_bounds__(256) agg_mean_kernel(
    const uint4* __restrict__ vsrc,    // [nsrc] rows of 8 x uint4 (128B)
    const int*   __restrict__ nbr,     // [nrows][KNBR]
    __half*      __restrict__ aggout,  // [nrows][DD] fp16
    int nrows)
{
    const int tid  = threadIdx.x;
    const int lane = tid & 31;
    const int warp = tid >> 5;
    const int rowA = blockIdx.x * 16 + warp * 2;
    const int rowB = rowA + 1;
    const int crA = min(rowA, nrows - 1);
    const int crB = min(rowB, nrows - 1);

    const int idxA = __ldg(nbr + (size_t)crA * KNBR + lane);
    const int idxB = __ldg(nbr + (size_t)crB * KNBR + lane);

    const int sub = lane >> 3;      // neighbor subgroup 0..3
    const int ch  = lane & 7;       // 16B chunk within 128B row

    __half2 zero = __float2half2_rn(0.f);
    __half2 aAcc[2][4], bAcc[2][4];
    #pragma unroll
    for (int s = 0; s < 2; ++s)
        #pragma unroll
        for (int j = 0; j < 4; ++j) { aAcc[s][j] = zero; bAcc[s][j] = zero; }

    #pragma unroll
    for (int i = 0; i < 8; ++i) {
        int nA = __shfl_sync(0xffffffffu, idxA, 4 * i + sub);
        int nB = __shfl_sync(0xffffffffu, idxB, 4 * i + sub);
        uint4 dA = __ldg(vsrc + (size_t)nA * 8 + ch);
        uint4 dB = __ldg(vsrc + (size_t)nB * 8 + ch);
        const __half2* hA = (const __half2*)&dA;
        const __half2* hB = (const __half2*)&dB;
        int s = i & 1;
        #pragma unroll
        for (int j = 0; j < 4; ++j) {
            aAcc[s][j] = __hadd2(aAcc[s][j], hA[j]);
            bAcc[s][j] = __hadd2(bAcc[s][j], hB[j]);
        }
    }

    // Merge even/odd sets (fp16 depth 5), convert to fp32.
    float fA[8], fB[8];
    #pragma unroll
    for (int j = 0; j < 4; ++j) {
        float2 va = __half22float2(__hadd2(aAcc[0][j], aAcc[1][j]));
        float2 vb = __half22float2(__hadd2(bAcc[0][j], bAcc[1][j]));
        fA[2 * j] = va.x;  fA[2 * j + 1] = va.y;
        fB[2 * j] = vb.x;  fB[2 * j + 1] = vb.y;
    }

    // Butterfly across the 4 subgroups (xor 8, xor 16): fp32.
    #pragma unroll
    for (int d = 8; d <= 16; d <<= 1) {
        #pragma unroll
        for (int j = 0; j < 8; ++j) {
            fA[j] += __shfl_xor_sync(0xffffffffu, fA[j], d);
            fB[j] += __shfl_xor_sync(0xffffffffu, fB[j], d);
        }
    }

    // All lanes now hold full sums of dims ch*8..ch*8+7.
    const float inv = 1.0f / KNBR;
    if (sub == 0 && rowA < nrows) {
        __half2 h[4];
        #pragma unroll
        for (int j = 0; j < 4; ++j)
            h[j] = __floats2half2_rn(fA[2 * j] * inv, fA[2 * j + 1] * inv);
        ((uint4*)aggout)[(size_t)rowA * 8 + ch] = *(uint4*)h;
    }
    if (sub == 1 && rowB < nrows) {
        __half2 h[4];
        #pragma unroll
        for (int j = 0; j < 4; ++j)
            h[j] = __floats2half2_rn(fB[2 * j] * inv, fB[2 * j + 1] * inv);
        ((uint4*)aggout)[(size_t)rowB * 8 + ch] = *(uint4*)h;
    }
}

// ---------------------------------------------------------------------------
// K3: pure GEMM  out = relu(A @ W + b), A fp16 [nrows,64], out fp16.
// 128 rows per block of 256 threads; thread = 4 rows x 8 cols, f32x2 FMA.
// ---------------------------------------------------------------------------
__global__ void __launch_bounds__(256) gemm64_kernel(
    const __half* __restrict__ A,
    const float*  __restrict__ W,
    const float*  __restrict__ bias,
    __half*       __restrict__ out,
    int nrows)
{
    __shared__ float  sW[DD * DD];       // 16 KB
    __shared__ __half sA[128 * 72];      // 18 KB, stride 72 halfs

    const int tid = threadIdx.x;
    #pragma unroll
    for (int i = tid; i < DD * DD / 4; i += 256)
        ((float4*)sW)[i] = __ldg((const float4*)W + i);

    const int rowbase = blockIdx.x * 128;
    for (int i = tid; i < 1024; i += 256) {
        int r = i >> 3, c = i & 7;
        int gr = min(rowbase + r, nrows - 1);
        uint4 v = __ldg((const uint4*)(A + (size_t)gr * DD) + c);
        *(uint4*)&sA[r * 72 + c * 8] = v;
    }
    __syncthreads();

    const int rp   = tid >> 3;        // rows 4rp .. 4rp+3
    const int col0 = (tid & 7) * 8;

    float4 bv0 = __ldg((const float4*)(bias + col0));
    float4 bv1 = __ldg((const float4*)(bias + col0 + 4));
    u64t bp[4];
    PACKU64(bp[0], bv0.x, bv0.y);  PACKU64(bp[1], bv0.z, bv0.w);
    PACKU64(bp[2], bv1.x, bv1.y);  PACKU64(bp[3], bv1.z, bv1.w);
    u64t acc[4][4];
    #pragma unroll
    for (int r = 0; r < 4; ++r)
        #pragma unroll
        for (int j = 0; j < 4; ++j) acc[r][j] = bp[j];

    #pragma unroll
    for (int k = 0; k < DD; k += 2) {
        ulonglong2 wA01 = *(const ulonglong2*)&sW[k * DD + col0];
        ulonglong2 wA23 = *(const ulonglong2*)&sW[k * DD + col0 + 4];
        ulonglong2 wB01 = *(const ulonglong2*)&sW[(k + 1) * DD + col0];
        ulonglong2 wB23 = *(const ulonglong2*)&sW[(k + 1) * DD + col0 + 4];
        #pragma unroll
        for (int r = 0; r < 4; ++r) {
            __half2 ah = *(const __half2*)&sA[(4 * rp + r) * 72 + k];
            float2 af = __half22float2(ah);
            u64t s0, s1;
            SPLATF64(s0, af.x);
            SPLATF64(s1, af.y);
            FFMA2(acc[r][0], s0, wA01.x);  FFMA2(acc[r][1], s0, wA01.y);
            FFMA2(acc[r][2], s0, wA23.x);  FFMA2(acc[r][3], s0, wA23.y);
            FFMA2(acc[r][0], s1, wB01.x);  FFMA2(acc[r][1], s1, wB01.y);
            FFMA2(acc[r][2], s1, wB23.x);  FFMA2(acc[r][3], s1, wB23.y);
        }
    }

    #pragma unroll
    for (int r = 0; r < 4; ++r) {
        int grow = rowbase + 4 * rp + r;
        if (grow >= nrows) continue;
        __half2 h[4];
        #pragma unroll
        for (int j = 0; j < 4; ++j) {
            float lo, hi;
            UNPACKF64(lo, hi, acc[r][j]);
            h[j] = __floats2half2_rn(fmaxf(lo, 0.f), fmaxf(hi, 0.f));
        }
        *(uint4*)(out + (size_t)grow * DD + col0) = *(uint4*)h;
    }
}

// ---------------------------------------------------------------------------
// K4: fused agg+GEMM for the seed layer (8192 rows), fp16 in, fp32 out.
// (R5 structure — small kernel, fine as is.)
// ---------------------------------------------------------------------------
__global__ void __launch_bounds__(256) seed_kernel(
    const __half2* __restrict__ vsrc,
    const int*     __restrict__ nbr,
    const float*   __restrict__ W,
    const float*   __restrict__ bias,
    float*         __restrict__ outp,
    int nrows)
{
    __shared__ float sW[DD * DD];
    __shared__ float sAgg[64][66];

    const int tid  = threadIdx.x;
    const int lane = tid & 31;
    const int warp = tid >> 5;

    #pragma unroll
    for (int i = tid; i < DD * DD / 4; i += 256)
        ((float4*)sW)[i] = __ldg((const float4*)W + i);

    const int rowbase = blockIdx.x * 64 + warp * 8;
    #pragma unroll 1
    for (int rr = 0; rr < 8; rr += 2) {
        int rA = rowbase + rr;
        int ca = min(rA, nrows - 1);
        int cb = min(rA + 1, nrows - 1);
        int idxA = __ldg(nbr + (size_t)ca * KNBR + lane);
        int idxB = __ldg(nbr + (size_t)cb * KNBR + lane);

        float sxA = 0.f, syA = 0.f, sxB = 0.f, syB = 0.f;
        #pragma unroll
        for (int k = 0; k < KNBR; k += 2) {
            int a0 = __shfl_sync(0xffffffffu, idxA, k);
            int a1 = __shfl_sync(0xffffffffu, idxA, k + 1);
            int b0 = __shfl_sync(0xffffffffu, idxB, k);
            int b1 = __shfl_sync(0xffffffffu, idxB, k + 1);
            __half2 hA0 = __ldg(vsrc + (size_t)a0 * 32 + lane);
            __half2 hA1 = __ldg(vsrc + (size_t)a1 * 32 + lane);
            __half2 hB0 = __ldg(vsrc + (size_t)b0 * 32 + lane);
            __half2 hB1 = __ldg(vsrc + (size_t)b1 * 32 + lane);
            float2 fA = __half22float2(__hadd2(hA0, hA1));
            float2 fB = __half22float2(__hadd2(hB0, hB1));
            sxA += fA.x;  syA += fA.y;
            sxB += fB.x;  syB += fB.y;
        }
        const float inv = 1.0f / KNBR;
        *(float2*)&sAgg[warp * 8 + rr][2 * lane]     = make_float2(sxA * inv, syA * inv);
        *(float2*)&sAgg[warp * 8 + rr + 1][2 * lane] = make_float2(sxB * inv, syB * inv);
    }
    __syncthreads();

    const int rp   = tid >> 3;
    const int col0 = (tid & 7) * 8;

    float4 bv0 = __ldg((const float4*)(bias + col0));
    float4 bv1 = __ldg((const float4*)(bias + col0 + 4));
    u64t acc0[4], acc1[4];
    PACKU64(acc0[0], bv0.x, bv0.y);  PACKU64(acc0[1], bv0.z, bv0.w);
    PACKU64(acc0[2], bv1.x, bv1.y);  PACKU64(acc0[3], bv1.z, bv1.w);
    acc1[0] = acc0[0];  acc1[1] = acc0[1];  acc1[2] = acc0[2];  acc1[3] = acc0[3];

    #pragma unroll
    for (int k = 0; k < DD; ++k) {
        float a0 = sAgg[2 * rp][k];
        float a1 = sAgg[2 * rp + 1][k];
        u64t s0, s1;
        SPLATF64(s0, a0);
        SPLATF64(s1, a1);
        const ulonglong2 w01 = *(const ulonglong2*)&sW[k * DD + col0];
        const ulonglong2 w23 = *(const ulonglong2*)&sW[k * DD + col0 + 4];
        FFMA2(acc0[0], s0, w01.x);  FFMA2(acc0[1], s0, w01.y);
        FFMA2(acc0[2], s0, w23.x);  FFMA2(acc0[3], s0, w23.y);
        FFMA2(acc1[0], s1, w01.x);  FFMA2(acc1[1], s1, w01.y);
        FFMA2(acc1[2], s1, w23.x);  FFMA2(acc1[3], s1, w23.y);
    }

    #pragma unroll
    for (int r = 0; r < 2; ++r) {
        int grow = blockIdx.x * 64 + 2 * rp + r;
        if (grow >= nrows) continue;
        const u64t* acc = r ? acc1 : acc0;
        float* op = (float*)outp + (size_t)grow * DD + col0;
        #pragma unroll
        for (int j = 0; j < 4; ++j) {
            float lo, hi;
            UNPACKF64(lo, hi, acc[j]);
            op[2 * j]     = fmaxf(lo, 0.f);
            op[2 * j + 1] = fmaxf(hi, 0.f);
        }
    }
}

// ---------------------------------------------------------------------------
// Inputs: 0 feats, 1 W0, 2 b0, 3 W1, 4 b1, 5 neigh_idx0, 6 neigh_idx1,
//         7 node_ids1 (unused), 8 node_ids2
// ---------------------------------------------------------------------------
extern "C" void kernel_launch(void* const* d_in, const int* in_sizes, int n_in,
                              void* d_out, int out_size)
{
    const float* feats      = (const float*)d_in[0];
    const float* W0         = (const float*)d_in[1];
    const float* b0         = (const float*)d_in[2];
    const float* W1         = (const float*)d_in[3];
    const float* b1         = (const float*)d_in[4];
    const int*   neigh_idx0 = (const int*)  d_in[5];
    const int*   neigh_idx1 = (const int*)  d_in[6];
    const int*   node_ids2  = (const int*)  d_in[8];
    float*       out        = (float*)d_out;

    __half* v2h;  cudaGetSymbolAddress((void**)&v2h,  g_v2h);
    __half* agg1; cudaGetSymbolAddress((void**)&agg1, g_agg1);
    __half* h1h;  cudaGetSymbolAddress((void**)&h1h,  g_h1h);

    {
        const int half_total = (N2V / 2) * (DD / 4);
        gather_v2h_kernel<<<(half_total + 255) / 256, 256>>>(feats, node_ids2);
    }
    agg_mean_kernel<<<(N1V + 15) / 16, 256>>>(
        (const uint4*)v2h, neigh_idx1, agg1, N1V);
    gemm64_kernel<<<(N1V + 127) / 128, 256>>>(
        agg1, W0, b0, h1h, N1V);
    seed_kernel<<<(N0V + 63) / 64, 256>>>(
        (const __half2*)h1h, neigh_idx0, W1, b1, out, N0V);
}